// round 9
// baseline (speedup 1.0000x reference)
#include <cuda_runtime.h>
#include <cuda_bf16.h>

// Problem constants (shapes fixed by the reference setup_inputs)
#define BSZ   4096
#define NTOK  49
#define CDIM  384
#define NH    12
#define HD    32
#define NWIN  64
#define MROWS (BSZ * NTOK)          // 200704
#define QKVN  (3 * CDIM)            // 1152

// Scratch (allocation-free rule: __device__ globals)
__device__ float g_qkv[(size_t)MROWS * QKVN];   // ~925 MB
__device__ float g_att[(size_t)MROWS * CDIM];   // ~308 MB

// ---------------------------------------------------------------------------
// bf16-split helpers
// ---------------------------------------------------------------------------
// Pack (x, y) -> bf16x2 "big" (lo = x, hi = y) and bf16x2 "small"
// (residual r = v - bf16(v), re-rounded). Residual <= 2^-9 * |v|.
__device__ __forceinline__ void bf_split2(float x, float y,
                                          unsigned& big, unsigned& sml) {
    unsigned p;
    asm("cvt.rn.bf16x2.f32 %0, %1, %2;" : "=r"(p) : "f"(y), "f"(x)); // hi=y, lo=x
    big = p;
    float xb = __uint_as_float(p << 16);          // bf16(x) as f32
    float yb = __uint_as_float(p & 0xffff0000u);  // bf16(y) as f32
    float rx = x - xb;                            // exact in f32
    float ry = y - yb;
    asm("cvt.rn.bf16x2.f32 %0, %1, %2;" : "=r"(sml) : "f"(ry), "f"(rx));
}

__device__ __forceinline__ void mma16(float* c,
                                      const unsigned* a, const unsigned* b) {
    asm volatile(
        "mma.sync.aligned.m16n8k16.row.col.f32.bf16.bf16.f32 "
        "{%0,%1,%2,%3}, {%4,%5,%6,%7}, {%8,%9}, {%0,%1,%2,%3};"
        : "+f"(c[0]), "+f"(c[1]), "+f"(c[2]), "+f"(c[3])
        : "r"(a[0]), "r"(a[1]), "r"(a[2]), "r"(a[3]), "r"(b[0]), "r"(b[1]));
}

// ---------------------------------------------------------------------------
// Tensor-core SGEMM (bf16x3 emulation): C[M,N] = A[M,K] @ B[K,N] + bias[N]
// Products {A0B0, A0B1, A1B0} of the one-time bf16 splits -> rel err ~<1e-4.
// Split happens ONCE at staging: smem holds big/small bf16x2 tiles, k-pairs
// packed per uint32. Block tile 128x64, 8 warps (4 M x 2 N), warp tile 32x32,
// K-tile 16, register-prefetch double buffering, one barrier per k-tile.
// Requires M%128==0, N%64==0, K%16==0 (true for both call sites).
// ---------------------------------------------------------------------------
#define KP 12   // uint32 pitch per row (8 k-pairs + 4 pad): fragment LDS banks
                // g*12+tig(+4) mod 32 are 32-distinct across the warp

__global__ __launch_bounds__(256, 2) void gemm_bf16x3(
    const float* __restrict__ A, const float* __restrict__ B,
    const float* __restrict__ bias, float* __restrict__ C,
    int M, int N, int K)
{
    __shared__ unsigned Ab[2][128 * KP];   // A big   [row][kpair]
    __shared__ unsigned Al[2][128 * KP];   // A small
    __shared__ unsigned Bb[2][64 * KP];    // B big   [col][kpair]  (transposed)
    __shared__ unsigned Bl[2][64 * KP];    // B small

    const int tid  = threadIdx.x;
    const int wid  = tid >> 5;
    const int lane = tid & 31;
    const int g    = lane >> 2;      // groupID (0..7)
    const int tig  = lane & 3;       // thread-in-group (0..3)
    const int wm   = wid & 3;        // warp m index (0..3)
    const int wn   = wid >> 2;       // warp n index (0..1)

    const int row0 = blockIdx.y * 128;
    const int col0 = blockIdx.x * 64;

    // Staging coordinates.
    // A tile: 128 rows x 4 k-float4 = 512 slots; 2 per thread
    const int a_r0 = (tid + 0)   >> 2, a_q0 = (tid + 0)   & 3;
    const int a_r1 = (tid + 256) >> 2, a_q1 = (tid + 256) & 3;
    // B tile: 8 k-pairs x 64 cols = 512 cells; 2 per thread (n fastest -> coalesced)
    const int b_n0 = (tid + 0)   & 63, b_p0 = (tid + 0)   >> 6;
    const int b_n1 = (tid + 256) & 63, b_p1 = (tid + 256) >> 6;

    const float* Ag0 = A + (size_t)(row0 + a_r0) * K + a_q0 * 4;
    const float* Ag1 = A + (size_t)(row0 + a_r1) * K + a_q1 * 4;
    const float* Bg0 = B + (size_t)(2 * b_p0) * N + col0 + b_n0;
    const float* Bg1 = B + (size_t)(2 * b_p1) * N + col0 + b_n1;

    float acc[2][4][4];
    #pragma unroll
    for (int mt = 0; mt < 2; mt++)
        #pragma unroll
        for (int nt = 0; nt < 4; nt++)
            #pragma unroll
            for (int e = 0; e < 4; e++) acc[mt][nt][e] = 0.0f;

    const int KT = K >> 4;   // 16-wide k tiles (24 or 72 here)

    // Prefetch registers for one tile
    float4 pa0, pa1;
    float  pb00, pb01, pb10, pb11;

    // ---- Prologue: load tile 0, convert into stage 0 ----
    pa0  = *(const float4*)(Ag0);
    pa1  = *(const float4*)(Ag1);
    pb00 = Bg0[0]; pb01 = Bg0[N];
    pb10 = Bg1[0]; pb11 = Bg1[N];
    {
        unsigned h0, l0, h1, l1;
        bf_split2(pa0.x, pa0.y, h0, l0); bf_split2(pa0.z, pa0.w, h1, l1);
        Ab[0][a_r0 * KP + 2 * a_q0] = h0; Ab[0][a_r0 * KP + 2 * a_q0 + 1] = h1;
        Al[0][a_r0 * KP + 2 * a_q0] = l0; Al[0][a_r0 * KP + 2 * a_q0 + 1] = l1;
        bf_split2(pa1.x, pa1.y, h0, l0); bf_split2(pa1.z, pa1.w, h1, l1);
        Ab[0][a_r1 * KP + 2 * a_q1] = h0; Ab[0][a_r1 * KP + 2 * a_q1 + 1] = h1;
        Al[0][a_r1 * KP + 2 * a_q1] = l0; Al[0][a_r1 * KP + 2 * a_q1 + 1] = l1;
        bf_split2(pb00, pb01, h0, l0);
        Bb[0][b_n0 * KP + b_p0] = h0; Bl[0][b_n0 * KP + b_p0] = l0;
        bf_split2(pb10, pb11, h0, l0);
        Bb[0][b_n1 * KP + b_p1] = h0; Bl[0][b_n1 * KP + b_p1] = l0;
    }

    for (int kt = 0; kt < KT; kt++) {
        const int  cur = kt & 1;
        const int  nxt = cur ^ 1;
        const bool has_next = (kt + 1) < KT;

        if (has_next) {   // issue next tile's global loads early
            const int kb = (kt + 1) * 16;
            pa0  = *(const float4*)(Ag0 + kb);
            pa1  = *(const float4*)(Ag1 + kb);
            pb00 = Bg0[(size_t)kb * N]; pb01 = Bg0[(size_t)(kb + 1) * N];
            pb10 = Bg1[(size_t)kb * N]; pb11 = Bg1[(size_t)(kb + 1) * N];
        }

        // All warps finished reading stage nxt (iteration kt-1) and stage cur's
        // stores (iteration kt-1 / prologue) are visible.
        __syncthreads();

        if (has_next) {   // convert + store next tile into stage nxt
            unsigned h0, l0, h1, l1;
            bf_split2(pa0.x, pa0.y, h0, l0); bf_split2(pa0.z, pa0.w, h1, l1);
            Ab[nxt][a_r0 * KP + 2 * a_q0] = h0; Ab[nxt][a_r0 * KP + 2 * a_q0 + 1] = h1;
            Al[nxt][a_r0 * KP + 2 * a_q0] = l0; Al[nxt][a_r0 * KP + 2 * a_q0 + 1] = l1;
            bf_split2(pa1.x, pa1.y, h0, l0); bf_split2(pa1.z, pa1.w, h1, l1);
            Ab[nxt][a_r1 * KP + 2 * a_q1] = h0; Ab[nxt][a_r1 * KP + 2 * a_q1 + 1] = h1;
            Al[nxt][a_r1 * KP + 2 * a_q1] = l0; Al[nxt][a_r1 * KP + 2 * a_q1 + 1] = l1;
            bf_split2(pb00, pb01, h0, l0);
            Bb[nxt][b_n0 * KP + b_p0] = h0; Bl[nxt][b_n0 * KP + b_p0] = l0;
            bf_split2(pb10, pb11, h0, l0);
            Bb[nxt][b_n1 * KP + b_p1] = h0; Bl[nxt][b_n1 * KP + b_p1] = l0;
        }

        // ---- One m16n8k16 per (mt, nt) per split-product from stage cur ----
        unsigned abig[2][4], asml[2][4], bbig[4][2], bsml[4][2];
        #pragma unroll
        for (int mt = 0; mt < 2; mt++) {
            const int r0 = (wm * 32 + mt * 16 + g) * KP;
            const int r1 = r0 + 8 * KP;
            abig[mt][0] = Ab[cur][r0 + tig];     abig[mt][1] = Ab[cur][r1 + tig];
            abig[mt][2] = Ab[cur][r0 + tig + 4]; abig[mt][3] = Ab[cur][r1 + tig + 4];
            asml[mt][0] = Al[cur][r0 + tig];     asml[mt][1] = Al[cur][r1 + tig];
            asml[mt][2] = Al[cur][r0 + tig + 4]; asml[mt][3] = Al[cur][r1 + tig + 4];
        }
        #pragma unroll
        for (int nt = 0; nt < 4; nt++) {
            const int cb = (wn * 32 + nt * 8 + g) * KP;
            bbig[nt][0] = Bb[cur][cb + tig]; bbig[nt][1] = Bb[cur][cb + tig + 4];
            bsml[nt][0] = Bl[cur][cb + tig]; bsml[nt][1] = Bl[cur][cb + tig + 4];
        }
        #pragma unroll
        for (int mt = 0; mt < 2; mt++)
            #pragma unroll
            for (int nt = 0; nt < 4; nt++) {
                mma16(acc[mt][nt], abig[mt], bbig[nt]);   // big*big
                mma16(acc[mt][nt], abig[mt], bsml[nt]);   // big*small
                mma16(acc[mt][nt], asml[mt], bbig[nt]);   // small*big
            }
    }

    // ---- Epilogue: += bias, float2 stores ----
    #pragma unroll
    for (int mt = 0; mt < 2; mt++) {
        const int r = row0 + wm * 32 + mt * 16 + g;
        #pragma unroll
        for (int nt = 0; nt < 4; nt++) {
            const int c = col0 + wn * 32 + nt * 8 + tig * 2;
            const float2 vb = *(const float2*)(bias + c);
            float2 lo, hi;
            lo.x = acc[mt][nt][0] + vb.x; lo.y = acc[mt][nt][1] + vb.y;
            hi.x = acc[mt][nt][2] + vb.x; hi.y = acc[mt][nt][3] + vb.y;
            *(float2*)(C + (size_t)r * N + c)       = lo;
            *(float2*)(C + (size_t)(r + 8) * N + c) = hi;
        }
    }
}

// ---------------------------------------------------------------------------
// Fused window attention: one block per (head h = blockIdx.x, window b = blockIdx.y)
//   scores = scale*q@k^T + rel_pos_bias + shift_mask; softmax; out = P@v
// rel-pos index arithmetically: idx = (ih-jh+6)*13 + (iw-jw+6); bias = bt[idx*12+h].
// Mask window index = b % 64.
// q/k pitch 36 floats (144B, 16B-aligned rows; float4-pitch 9 odd -> conflict-
// free k[j] vector loads). s pitch 52 (208B rows, 16B-aligned -> float4 reads).
// v stored TRANSPOSED vt[d][n], pitch 52 (float4-pitch 13 odd -> conflict-free
// per-lane row reads in P@V).
// ---------------------------------------------------------------------------
#define QP 36
#define SP 52
#define VP 52

__global__ __launch_bounds__(256) void win_attn(
    const float* __restrict__ qkv, const float* __restrict__ mask,
    const float* __restrict__ bt, float* __restrict__ out)
{
    __shared__ float q[NTOK][QP];
    __shared__ float k[NTOK][QP];
    __shared__ float vt[HD][VP];     // transposed: vt[d][n]
    __shared__ float s[NTOK][SP];
    __shared__ float btc[169];

    const int h   = blockIdx.x;
    const int b   = blockIdx.y;
    const int tid = threadIdx.x;
    const float scale = 0.17677669529663687f;   // 1/sqrt(32)

    const size_t base = (size_t)b * NTOK * QKVN + (size_t)h * HD;
    for (int idx = tid; idx < NTOK * HD; idx += 256) {
        int n = idx >> 5, d = idx & 31;
        size_t o = base + (size_t)n * QKVN + d;
        q[n][d]  = qkv[o] * scale;
        k[n][d]  = qkv[o + CDIM];
        vt[d][n] = qkv[o + 2 * CDIM];
    }
    for (int t = tid; t < 169; t += 256) btc[t] = bt[t * NH + h];
    __syncthreads();

    // Scores + bias + mask. Warp w handles rows i = w, w+8, ...; lanes sweep j.
    // q row hoisted into registers once per row; k rows read as float4.
    const int wid  = tid >> 5;
    const int lane = tid & 31;
    const float* mrow = mask + (size_t)(b & (NWIN - 1)) * NTOK * NTOK;

    for (int i = wid; i < NTOK; i += 8) {
        float4 qr[8];
        #pragma unroll
        for (int d4 = 0; d4 < 8; d4++) qr[d4] = *(const float4*)(&q[i][d4 * 4]);
        const int ih = i / 7, iw = i % 7;
        for (int j = lane; j < NTOK; j += 32) {
            float acc = 0.0f;
            #pragma unroll
            for (int d4 = 0; d4 < 8; d4++) {
                float4 kr = *(const float4*)(&k[j][d4 * 4]);
                acc = fmaf(qr[d4].x, kr.x, acc);
                acc = fmaf(qr[d4].y, kr.y, acc);
                acc = fmaf(qr[d4].z, kr.z, acc);
                acc = fmaf(qr[d4].w, kr.w, acc);
            }
            int ridx = (ih - j / 7 + 6) * 13 + (iw - j % 7 + 6);
            s[i][j] = acc + btc[ridx] + mrow[i * NTOK + j];
        }
    }
    __syncthreads();

    // Row softmax: one warp per row, 8 warps cycle over 49 rows
    for (int i = wid; i < NTOK; i += 8) {
        float m = -1e30f;
        for (int j = lane; j < NTOK; j += 32) m = fmaxf(m, s[i][j]);
        #pragma unroll
        for (int o = 16; o > 0; o >>= 1) m = fmaxf(m, __shfl_xor_sync(0xffffffffu, m, o));
        float sum = 0.0f;
        for (int j = lane; j < NTOK; j += 32) {
            float p = __expf(s[i][j] - m);
            s[i][j] = p;
            sum += p;
        }
        #pragma unroll
        for (int o = 16; o > 0; o >>= 1) sum += __shfl_xor_sync(0xffffffffu, sum, o);
        float inv = 1.0f / sum;
        for (int j = lane; j < NTOK; j += 32) s[i][j] *= inv;
    }
    __syncthreads();

    // out = P @ v. Warp w handles row i; lane = output channel d.
    // Per 4 j-steps: one float4 broadcast of s + one float4 of vt -> 4 FMA.
    for (int i = wid; i < NTOK; i += 8) {
        float acc = 0.0f;
        #pragma unroll
        for (int j4 = 0; j4 < 12; j4++) {
            float4 sv = *(const float4*)(&s[i][j4 * 4]);        // broadcast
            float4 vv = *(const float4*)(&vt[lane][j4 * 4]);    // conflict-free
            acc = fmaf(sv.x, vv.x, acc);
            acc = fmaf(sv.y, vv.y, acc);
            acc = fmaf(sv.z, vv.z, acc);
            acc = fmaf(sv.w, vv.w, acc);
        }
        acc = fmaf(s[i][48], vt[lane][48], acc);                // j = 48 tail
        out[((size_t)b * NTOK + i) * CDIM + (size_t)h * HD + lane] = acc;
    }
}

// ---------------------------------------------------------------------------
// Launch: QKV GEMM -> fused attention -> proj GEMM
// ---------------------------------------------------------------------------
extern "C" void kernel_launch(void* const* d_in, const int* in_sizes, int n_in,
                              void* d_out, int out_size)
{
    const float* x      = (const float*)d_in[0];
    const float* mask   = (const float*)d_in[1];
    const float* qkv_w  = (const float*)d_in[2];
    const float* qkv_b  = (const float*)d_in[3];
    const float* proj_w = (const float*)d_in[4];
    const float* proj_b = (const float*)d_in[5];
    const float* btbl   = (const float*)d_in[6];
    float* out          = (float*)d_out;

    float *qkvp = nullptr, *attp = nullptr;
    cudaGetSymbolAddress((void**)&qkvp, g_qkv);
    cudaGetSymbolAddress((void**)&attp, g_att);

    // QKV: [200704 x 384] @ [384 x 1152] + bias
    gemm_bf16x3<<<dim3(QKVN / 64, MROWS / 128), 256>>>(
        x, qkv_w, qkv_b, qkvp, MROWS, QKVN, CDIM);

    // Fused window attention (one block per head x window)
    win_attn<<<dim3(NH, BSZ), 256>>>(qkvp, mask, btbl, attp);

    // Proj: [200704 x 384] @ [384 x 384] + bias
    gemm_bf16x3<<<dim3(CDIM / 64, MROWS / 128), 256>>>(
        attp, proj_w, proj_b, out, MROWS, CDIM, CDIM);
}

// round 12
// speedup vs baseline: 1.0642x; 1.0642x over previous
#include <cuda_runtime.h>
#include <cuda_bf16.h>

// Problem constants (shapes fixed by the reference setup_inputs)
#define BSZ   4096
#define NTOK  49
#define CDIM  384
#define NH    12
#define HD    32
#define NWIN  64
#define MROWS (BSZ * NTOK)          // 200704
#define QKVN  (3 * CDIM)            // 1152

// Scratch (allocation-free rule: __device__ globals)
__device__ float g_qkv[(size_t)MROWS * QKVN];   // ~925 MB
__device__ float g_att[(size_t)MROWS * CDIM];   // ~308 MB

// ---------------------------------------------------------------------------
// bf16-split helpers
// ---------------------------------------------------------------------------
// Pack (x, y) -> bf16x2 "big" (lo = x, hi = y) and bf16x2 "small"
// (residual r = v - bf16(v), re-rounded). Residual <= 2^-9 * |v|.
__device__ __forceinline__ void bf_split2(float x, float y,
                                          unsigned& big, unsigned& sml) {
    unsigned p;
    asm("cvt.rn.bf16x2.f32 %0, %1, %2;" : "=r"(p) : "f"(y), "f"(x)); // hi=y, lo=x
    big = p;
    float xb = __uint_as_float(p << 16);          // bf16(x) as f32
    float yb = __uint_as_float(p & 0xffff0000u);  // bf16(y) as f32
    float rx = x - xb;                            // exact in f32
    float ry = y - yb;
    asm("cvt.rn.bf16x2.f32 %0, %1, %2;" : "=r"(sml) : "f"(ry), "f"(rx));
}

__device__ __forceinline__ void mma16(float* c,
                                      const unsigned* a, const unsigned* b) {
    asm volatile(
        "mma.sync.aligned.m16n8k16.row.col.f32.bf16.bf16.f32 "
        "{%0,%1,%2,%3}, {%4,%5,%6,%7}, {%8,%9}, {%0,%1,%2,%3};"
        : "+f"(c[0]), "+f"(c[1]), "+f"(c[2]), "+f"(c[3])
        : "r"(a[0]), "r"(a[1]), "r"(a[2]), "r"(a[3]), "r"(b[0]), "r"(b[1]));
}

// ---------------------------------------------------------------------------
// Tensor-core SGEMM (bf16x3 emulation): C[M,N] = A[M,K] @ B[K,N] + bias[N]
// Products {A0B0, A0B1, A1B0} of the one-time bf16 splits -> rel err ~<1e-4.
// R9 ncu: L1=76.8% (binding), tensor=40.7% -> fragment-LDS-bound. Fix: warp
// tile 32x32 -> 32x64 (block 128x128): fragment loads/MMA 1.33 -> 1.0, and
// A-staging STS vectorized to STS.64. Split happens ONCE at staging; smem
// holds big/small bf16x2 tiles, k-pairs packed per uint32. 8 warps (4 M x 2 N),
// K-tile 16, register-prefetch double buffering, one barrier per k-tile.
// M%128==0, N%128==0, K%16==0 hold at both call sites.
// ---------------------------------------------------------------------------
#define KP 12   // uint32 pitch per row (8 k-pairs + 4 pad): fragment LDS banks
                // g*12+tig(+4) mod 32 are 32-distinct across the warp

__global__ __launch_bounds__(256, 2) void gemm_bf16x3(
    const float* __restrict__ A, const float* __restrict__ B,
    const float* __restrict__ bias, float* __restrict__ C,
    int M, int N, int K)
{
    __shared__ unsigned Ab[2][128 * KP];   // A big   [row][kpair]   12 KB
    __shared__ unsigned Al[2][128 * KP];   // A small               12 KB
    __shared__ unsigned Bb[2][128 * KP];   // B big   [col][kpair]  12 KB
    __shared__ unsigned Bl[2][128 * KP];   // B small               12 KB  (48 KB total)

    const int tid  = threadIdx.x;
    const int wid  = tid >> 5;
    const int lane = tid & 31;
    const int g    = lane >> 2;      // groupID (0..7)
    const int tig  = lane & 3;       // thread-in-group (0..3)
    const int wm   = wid & 3;        // warp m index (0..3)
    const int wn   = wid >> 2;       // warp n index (0..1)

    const int row0 = blockIdx.y * 128;
    const int col0 = blockIdx.x * 128;

    // Staging coordinates.
    // A tile: 128 rows x 4 k-float4 = 512 slots; 2 per thread
    const int a_r0 = (tid + 0)   >> 2, a_q0 = (tid + 0)   & 3;
    const int a_r1 = (tid + 256) >> 2, a_q1 = (tid + 256) & 3;
    // B tile: 8 k-pairs x 128 cols = 1024 cells; 4 per thread.
    // (tid + i*256): n = tid & 127 (same for all i), p = (tid>>7) + 2i.
    const int b_n  = tid & 127;
    const int b_pb = tid >> 7;       // 0 or 1

    const float* Ag0 = A + (size_t)(row0 + a_r0) * K + a_q0 * 4;
    const float* Ag1 = A + (size_t)(row0 + a_r1) * K + a_q1 * 4;
    const float* Bg  = B + col0 + b_n;

    float acc[2][8][4];
    #pragma unroll
    for (int mt = 0; mt < 2; mt++)
        #pragma unroll
        for (int nt = 0; nt < 8; nt++)
            #pragma unroll
            for (int e = 0; e < 4; e++) acc[mt][nt][e] = 0.0f;

    const int KT = K >> 4;   // 16-wide k tiles (24 or 72 here)

    // Prefetch registers for one tile
    float4 pa0, pa1;
    float  pb[4][2];

    // ---- Prologue: load tile 0, convert into stage 0 ----
    pa0 = *(const float4*)(Ag0);
    pa1 = *(const float4*)(Ag1);
    #pragma unroll
    for (int i = 0; i < 4; i++) {
        const int p = b_pb + 2 * i;
        pb[i][0] = Bg[(size_t)(2 * p)     * N];
        pb[i][1] = Bg[(size_t)(2 * p + 1) * N];
    }
    {
        unsigned h0, l0, h1, l1;
        bf_split2(pa0.x, pa0.y, h0, l0); bf_split2(pa0.z, pa0.w, h1, l1);
        *(uint2*)(&Ab[0][a_r0 * KP + 2 * a_q0]) = make_uint2(h0, h1);
        *(uint2*)(&Al[0][a_r0 * KP + 2 * a_q0]) = make_uint2(l0, l1);
        bf_split2(pa1.x, pa1.y, h0, l0); bf_split2(pa1.z, pa1.w, h1, l1);
        *(uint2*)(&Ab[0][a_r1 * KP + 2 * a_q1]) = make_uint2(h0, h1);
        *(uint2*)(&Al[0][a_r1 * KP + 2 * a_q1]) = make_uint2(l0, l1);
        #pragma unroll
        for (int i = 0; i < 4; i++) {
            const int p = b_pb + 2 * i;
            bf_split2(pb[i][0], pb[i][1], h0, l0);
            Bb[0][b_n * KP + p] = h0; Bl[0][b_n * KP + p] = l0;
        }
    }

    for (int kt = 0; kt < KT; kt++) {
        const int  cur = kt & 1;
        const int  nxt = cur ^ 1;
        const bool has_next = (kt + 1) < KT;

        if (has_next) {   // issue next tile's global loads early
            const int kb = (kt + 1) * 16;
            pa0 = *(const float4*)(Ag0 + kb);
            pa1 = *(const float4*)(Ag1 + kb);
            #pragma unroll
            for (int i = 0; i < 4; i++) {
                const int p = b_pb + 2 * i;
                pb[i][0] = Bg[(size_t)(kb + 2 * p)     * N];
                pb[i][1] = Bg[(size_t)(kb + 2 * p + 1) * N];
            }
        }

        // All warps finished reading stage nxt (iteration kt-1) and stage cur's
        // stores (iteration kt-1 / prologue) are visible.
        __syncthreads();

        if (has_next) {   // convert + store next tile into stage nxt
            unsigned h0, l0, h1, l1;
            bf_split2(pa0.x, pa0.y, h0, l0); bf_split2(pa0.z, pa0.w, h1, l1);
            *(uint2*)(&Ab[nxt][a_r0 * KP + 2 * a_q0]) = make_uint2(h0, h1);
            *(uint2*)(&Al[nxt][a_r0 * KP + 2 * a_q0]) = make_uint2(l0, l1);
            bf_split2(pa1.x, pa1.y, h0, l0); bf_split2(pa1.z, pa1.w, h1, l1);
            *(uint2*)(&Ab[nxt][a_r1 * KP + 2 * a_q1]) = make_uint2(h0, h1);
            *(uint2*)(&Al[nxt][a_r1 * KP + 2 * a_q1]) = make_uint2(l0, l1);
            #pragma unroll
            for (int i = 0; i < 4; i++) {
                const int p = b_pb + 2 * i;
                bf_split2(pb[i][0], pb[i][1], h0, l0);
                Bb[nxt][b_n * KP + p] = h0; Bl[nxt][b_n * KP + p] = l0;
            }
        }

        // ---- m16n8k16 MMAs from stage cur: A frags once, B streamed per nt ----
        unsigned abig[2][4], asml[2][4];
        #pragma unroll
        for (int mt = 0; mt < 2; mt++) {
            const int r0 = (wm * 32 + mt * 16 + g) * KP;
            const int r1 = r0 + 8 * KP;
            abig[mt][0] = Ab[cur][r0 + tig];     abig[mt][1] = Ab[cur][r1 + tig];
            abig[mt][2] = Ab[cur][r0 + tig + 4]; abig[mt][3] = Ab[cur][r1 + tig + 4];
            asml[mt][0] = Al[cur][r0 + tig];     asml[mt][1] = Al[cur][r1 + tig];
            asml[mt][2] = Al[cur][r0 + tig + 4]; asml[mt][3] = Al[cur][r1 + tig + 4];
        }
        #pragma unroll
        for (int nt = 0; nt < 8; nt++) {
            const int cb = (wn * 64 + nt * 8 + g) * KP;
            unsigned bb[2], bs[2];
            bb[0] = Bb[cur][cb + tig]; bb[1] = Bb[cur][cb + tig + 4];
            bs[0] = Bl[cur][cb + tig]; bs[1] = Bl[cur][cb + tig + 4];
            #pragma unroll
            for (int mt = 0; mt < 2; mt++) {
                mma16(acc[mt][nt], abig[mt], bb);   // big*big
                mma16(acc[mt][nt], abig[mt], bs);   // big*small
                mma16(acc[mt][nt], asml[mt], bb);   // small*big
            }
        }
    }

    // ---- Epilogue: += bias, float2 stores ----
    #pragma unroll
    for (int mt = 0; mt < 2; mt++) {
        const int r = row0 + wm * 32 + mt * 16 + g;
        #pragma unroll
        for (int nt = 0; nt < 8; nt++) {
            const int c = col0 + wn * 64 + nt * 8 + tig * 2;
            const float2 vb = *(const float2*)(bias + c);
            float2 lo, hi;
            lo.x = acc[mt][nt][0] + vb.x; lo.y = acc[mt][nt][1] + vb.y;
            hi.x = acc[mt][nt][2] + vb.x; hi.y = acc[mt][nt][3] + vb.y;
            *(float2*)(C + (size_t)r * N + c)       = lo;
            *(float2*)(C + (size_t)(r + 8) * N + c) = hi;
        }
    }
}

// ---------------------------------------------------------------------------
// Fused window attention: one block per (head h = blockIdx.x, window b = blockIdx.y)
//   scores = scale*q@k^T + rel_pos_bias + shift_mask; softmax; out = P@v
// rel-pos index arithmetically: idx = (ih-jh+6)*13 + (iw-jw+6); bias = bt[idx*12+h].
// Mask window index = b % 64.
// q/k pitch 36 floats (144B, 16B-aligned rows; float4-pitch 9 odd -> conflict-
// free k[j] vector loads). s pitch 52 (208B rows, 16B-aligned -> float4 reads).
// v stored TRANSPOSED vt[d][n], pitch 52 (float4-pitch 13 odd -> conflict-free
// per-lane row reads in P@V). Softmax stores UNNORMALIZED exp; 1/sum kept in
// sinv[] and folded into the P@V epilogue (saves the s *= inv pass).
// ---------------------------------------------------------------------------
#define QP 36
#define SP 52
#define VP 52

__global__ __launch_bounds__(256) void win_attn(
    const float* __restrict__ qkv, const float* __restrict__ mask,
    const float* __restrict__ bt, float* __restrict__ out)
{
    __shared__ float q[NTOK][QP];
    __shared__ float k[NTOK][QP];
    __shared__ float vt[HD][VP];     // transposed: vt[d][n]
    __shared__ float s[NTOK][SP];
    __shared__ float sinv[NTOK];     // per-row 1/sum
    __shared__ float btc[169];

    const int h   = blockIdx.x;
    const int b   = blockIdx.y;
    const int tid = threadIdx.x;
    const float scale = 0.17677669529663687f;   // 1/sqrt(32)

    const size_t base = (size_t)b * NTOK * QKVN + (size_t)h * HD;
    for (int idx = tid; idx < NTOK * HD; idx += 256) {
        int n = idx >> 5, d = idx & 31;
        size_t o = base + (size_t)n * QKVN + d;
        q[n][d]  = qkv[o] * scale;
        k[n][d]  = qkv[o + CDIM];
        vt[d][n] = qkv[o + 2 * CDIM];
    }
    for (int t = tid; t < 169; t += 256) btc[t] = bt[t * NH + h];
    __syncthreads();

    // Scores + bias + mask. Warp w handles rows i = w, w+8, ...; lanes sweep j.
    const int wid  = tid >> 5;
    const int lane = tid & 31;
    const float* mrow = mask + (size_t)(b & (NWIN - 1)) * NTOK * NTOK;

    for (int i = wid; i < NTOK; i += 8) {
        float4 qr[8];
        #pragma unroll
        for (int d4 = 0; d4 < 8; d4++) qr[d4] = *(const float4*)(&q[i][d4 * 4]);
        const int ih = i / 7, iw = i % 7;
        for (int j = lane; j < NTOK; j += 32) {
            float acc = 0.0f;
            #pragma unroll
            for (int d4 = 0; d4 < 8; d4++) {
                float4 kr = *(const float4*)(&k[j][d4 * 4]);
                acc = fmaf(qr[d4].x, kr.x, acc);
                acc = fmaf(qr[d4].y, kr.y, acc);
                acc = fmaf(qr[d4].z, kr.z, acc);
                acc = fmaf(qr[d4].w, kr.w, acc);
            }
            int ridx = (ih - j / 7 + 6) * 13 + (iw - j % 7 + 6);
            s[i][j] = acc + btc[ridx] + mrow[i * NTOK + j];
        }
    }
    __syncthreads();

    // Row softmax (unnormalized): one warp per row; stash 1/sum in sinv[i].
    for (int i = wid; i < NTOK; i += 8) {
        float m = -1e30f;
        for (int j = lane; j < NTOK; j += 32) m = fmaxf(m, s[i][j]);
        #pragma unroll
        for (int o = 16; o > 0; o >>= 1) m = fmaxf(m, __shfl_xor_sync(0xffffffffu, m, o));
        float sum = 0.0f;
        for (int j = lane; j < NTOK; j += 32) {
            float p = __expf(s[i][j] - m);
            s[i][j] = p;
            sum += p;
        }
        #pragma unroll
        for (int o = 16; o > 0; o >>= 1) sum += __shfl_xor_sync(0xffffffffu, sum, o);
        if (lane == 0) sinv[i] = 1.0f / sum;
    }
    __syncthreads();

    // out = (P @ v) * sinv[i]. Warp w handles row i; lane = output channel d.
    for (int i = wid; i < NTOK; i += 8) {
        float acc = 0.0f;
        #pragma unroll
        for (int j4 = 0; j4 < 12; j4++) {
            float4 sv = *(const float4*)(&s[i][j4 * 4]);        // broadcast
            float4 vv = *(const float4*)(&vt[lane][j4 * 4]);    // conflict-free
            acc = fmaf(sv.x, vv.x, acc);
            acc = fmaf(sv.y, vv.y, acc);
            acc = fmaf(sv.z, vv.z, acc);
            acc = fmaf(sv.w, vv.w, acc);
        }
        acc = fmaf(s[i][48], vt[lane][48], acc);                // j = 48 tail
        out[((size_t)b * NTOK + i) * CDIM + (size_t)h * HD + lane] = acc * sinv[i];
    }
}

// ---------------------------------------------------------------------------
// Launch: QKV GEMM -> fused attention -> proj GEMM
// ---------------------------------------------------------------------------
extern "C" void kernel_launch(void* const* d_in, const int* in_sizes, int n_in,
                              void* d_out, int out_size)
{
    const float* x      = (const float*)d_in[0];
    const float* mask   = (const float*)d_in[1];
    const float* qkv_w  = (const float*)d_in[2];
    const float* qkv_b  = (const float*)d_in[3];
    const float* proj_w = (const float*)d_in[4];
    const float* proj_b = (const float*)d_in[5];
    const float* btbl   = (const float*)d_in[6];
    float* out          = (float*)d_out;

    float *qkvp = nullptr, *attp = nullptr;
    cudaGetSymbolAddress((void**)&qkvp, g_qkv);
    cudaGetSymbolAddress((void**)&attp, g_att);

    // QKV: [200704 x 384] @ [384 x 1152] + bias
    gemm_bf16x3<<<dim3(QKVN / 128, MROWS / 128), 256>>>(
        x, qkv_w, qkv_b, qkvp, MROWS, QKVN, CDIM);

    // Fused window attention (one block per head x window)
    win_attn<<<dim3(NH, BSZ), 256>>>(qkvp, mask, btbl, attp);

    // Proj: [200704 x 384] @ [384 x 384] + bias
    gemm_bf16x3<<<dim3(CDIM / 128, MROWS / 128), 256>>>(
        attp, proj_w, proj_b, out, MROWS, CDIM, CDIM);
}

// round 16
// speedup vs baseline: 1.0784x; 1.0134x over previous
#include <cuda_runtime.h>
#include <cuda_bf16.h>

// Problem constants (shapes fixed by the reference setup_inputs)
#define BSZ   4096
#define NTOK  49
#define CDIM  384
#define NH    12
#define HD    32
#define NWIN  64
#define MROWS (BSZ * NTOK)          // 200704
#define QKVN  (3 * CDIM)            // 1152

// Scratch (allocation-free rule: __device__ globals)
__device__ float g_qkv[(size_t)MROWS * QKVN];   // ~925 MB
__device__ float g_att[(size_t)MROWS * CDIM];   // ~308 MB

// ---------------------------------------------------------------------------
// bf16-split helpers
// ---------------------------------------------------------------------------
__device__ __forceinline__ void bf_split2(float x, float y,
                                          unsigned& big, unsigned& sml) {
    unsigned p;
    asm("cvt.rn.bf16x2.f32 %0, %1, %2;" : "=r"(p) : "f"(y), "f"(x)); // hi=y, lo=x
    big = p;
    float xb = __uint_as_float(p << 16);
    float yb = __uint_as_float(p & 0xffff0000u);
    float rx = x - xb;
    float ry = y - yb;
    asm("cvt.rn.bf16x2.f32 %0, %1, %2;" : "=r"(sml) : "f"(ry), "f"(rx));
}

__device__ __forceinline__ void mma16(float* c,
                                      const unsigned* a, const unsigned* b) {
    asm volatile(
        "mma.sync.aligned.m16n8k16.row.col.f32.bf16.bf16.f32 "
        "{%0,%1,%2,%3}, {%4,%5,%6,%7}, {%8,%9}, {%0,%1,%2,%3};"
        : "+f"(c[0]), "+f"(c[1]), "+f"(c[2]), "+f"(c[3])
        : "r"(a[0]), "r"(a[1]), "r"(a[2]), "r"(a[3]), "r"(b[0]), "r"(b[1]));
}

// ---------------------------------------------------------------------------
// Tensor-core SGEMM (bf16x3 emulation) — R12 proven version (4103us pass).
// Block tile 128x128, 8 warps (4 M x 2 N), warp tile 32x64, K-tile 16,
// register-prefetch double buffering, one barrier per k-tile.
// ---------------------------------------------------------------------------
#define KP 12

__global__ __launch_bounds__(256, 2) void gemm_bf16x3(
    const float* __restrict__ A, const float* __restrict__ B,
    const float* __restrict__ bias, float* __restrict__ C,
    int M, int N, int K)
{
    __shared__ unsigned Ab[2][128 * KP];
    __shared__ unsigned Al[2][128 * KP];
    __shared__ unsigned Bb[2][128 * KP];
    __shared__ unsigned Bl[2][128 * KP];

    const int tid  = threadIdx.x;
    const int wid  = tid >> 5;
    const int lane = tid & 31;
    const int g    = lane >> 2;
    const int tig  = lane & 3;
    const int wm   = wid & 3;
    const int wn   = wid >> 2;

    const int row0 = blockIdx.y * 128;
    const int col0 = blockIdx.x * 128;

    const int a_r0 = (tid + 0)   >> 2, a_q0 = (tid + 0)   & 3;
    const int a_r1 = (tid + 256) >> 2, a_q1 = (tid + 256) & 3;
    const int b_n  = tid & 127;
    const int b_pb = tid >> 7;

    const float* Ag0 = A + (size_t)(row0 + a_r0) * K + a_q0 * 4;
    const float* Ag1 = A + (size_t)(row0 + a_r1) * K + a_q1 * 4;
    const float* Bg  = B + col0 + b_n;

    float acc[2][8][4];
    #pragma unroll
    for (int mt = 0; mt < 2; mt++)
        #pragma unroll
        for (int nt = 0; nt < 8; nt++)
            #pragma unroll
            for (int e = 0; e < 4; e++) acc[mt][nt][e] = 0.0f;

    const int KT = K >> 4;

    float4 pa0, pa1;
    float  pb[4][2];

    pa0 = *(const float4*)(Ag0);
    pa1 = *(const float4*)(Ag1);
    #pragma unroll
    for (int i = 0; i < 4; i++) {
        const int p = b_pb + 2 * i;
        pb[i][0] = Bg[(size_t)(2 * p)     * N];
        pb[i][1] = Bg[(size_t)(2 * p + 1) * N];
    }
    {
        unsigned h0, l0, h1, l1;
        bf_split2(pa0.x, pa0.y, h0, l0); bf_split2(pa0.z, pa0.w, h1, l1);
        *(uint2*)(&Ab[0][a_r0 * KP + 2 * a_q0]) = make_uint2(h0, h1);
        *(uint2*)(&Al[0][a_r0 * KP + 2 * a_q0]) = make_uint2(l0, l1);
        bf_split2(pa1.x, pa1.y, h0, l0); bf_split2(pa1.z, pa1.w, h1, l1);
        *(uint2*)(&Ab[0][a_r1 * KP + 2 * a_q1]) = make_uint2(h0, h1);
        *(uint2*)(&Al[0][a_r1 * KP + 2 * a_q1]) = make_uint2(l0, l1);
        #pragma unroll
        for (int i = 0; i < 4; i++) {
            const int p = b_pb + 2 * i;
            bf_split2(pb[i][0], pb[i][1], h0, l0);
            Bb[0][b_n * KP + p] = h0; Bl[0][b_n * KP + p] = l0;
        }
    }

    for (int kt = 0; kt < KT; kt++) {
        const int  cur = kt & 1;
        const int  nxt = cur ^ 1;
        const bool has_next = (kt + 1) < KT;

        if (has_next) {
            const int kb = (kt + 1) * 16;
            pa0 = *(const float4*)(Ag0 + kb);
            pa1 = *(const float4*)(Ag1 + kb);
            #pragma unroll
            for (int i = 0; i < 4; i++) {
                const int p = b_pb + 2 * i;
                pb[i][0] = Bg[(size_t)(kb + 2 * p)     * N];
                pb[i][1] = Bg[(size_t)(kb + 2 * p + 1) * N];
            }
        }

        __syncthreads();

        if (has_next) {
            unsigned h0, l0, h1, l1;
            bf_split2(pa0.x, pa0.y, h0, l0); bf_split2(pa0.z, pa0.w, h1, l1);
            *(uint2*)(&Ab[nxt][a_r0 * KP + 2 * a_q0]) = make_uint2(h0, h1);
            *(uint2*)(&Al[nxt][a_r0 * KP + 2 * a_q0]) = make_uint2(l0, l1);
            bf_split2(pa1.x, pa1.y, h0, l0); bf_split2(pa1.z, pa1.w, h1, l1);
            *(uint2*)(&Ab[nxt][a_r1 * KP + 2 * a_q1]) = make_uint2(h0, h1);
            *(uint2*)(&Al[nxt][a_r1 * KP + 2 * a_q1]) = make_uint2(l0, l1);
            #pragma unroll
            for (int i = 0; i < 4; i++) {
                const int p = b_pb + 2 * i;
                bf_split2(pb[i][0], pb[i][1], h0, l0);
                Bb[nxt][b_n * KP + p] = h0; Bl[nxt][b_n * KP + p] = l0;
            }
        }

        unsigned abig[2][4], asml[2][4];
        #pragma unroll
        for (int mt = 0; mt < 2; mt++) {
            const int r0 = (wm * 32 + mt * 16 + g) * KP;
            const int r1 = r0 + 8 * KP;
            abig[mt][0] = Ab[cur][r0 + tig];     abig[mt][1] = Ab[cur][r1 + tig];
            abig[mt][2] = Ab[cur][r0 + tig + 4]; abig[mt][3] = Ab[cur][r1 + tig + 4];
            asml[mt][0] = Al[cur][r0 + tig];     asml[mt][1] = Al[cur][r1 + tig];
            asml[mt][2] = Al[cur][r0 + tig + 4]; asml[mt][3] = Al[cur][r1 + tig + 4];
        }
        #pragma unroll
        for (int nt = 0; nt < 8; nt++) {
            const int cb = (wn * 64 + nt * 8 + g) * KP;
            unsigned bb[2], bs[2];
            bb[0] = Bb[cur][cb + tig]; bb[1] = Bb[cur][cb + tig + 4];
            bs[0] = Bl[cur][cb + tig]; bs[1] = Bl[cur][cb + tig + 4];
            #pragma unroll
            for (int mt = 0; mt < 2; mt++) {
                mma16(acc[mt][nt], abig[mt], bb);
                mma16(acc[mt][nt], abig[mt], bs);
                mma16(acc[mt][nt], asml[mt], bb);
            }
        }
    }

    #pragma unroll
    for (int mt = 0; mt < 2; mt++) {
        const int r = row0 + wm * 32 + mt * 16 + g;
        #pragma unroll
        for (int nt = 0; nt < 8; nt++) {
            const int c = col0 + wn * 64 + nt * 8 + tig * 2;
            const float2 vb = *(const float2*)(bias + c);
            float2 lo, hi;
            lo.x = acc[mt][nt][0] + vb.x; lo.y = acc[mt][nt][1] + vb.y;
            hi.x = acc[mt][nt][2] + vb.x; hi.y = acc[mt][nt][3] + vb.y;
            *(float2*)(C + (size_t)r * N + c)       = lo;
            *(float2*)(C + (size_t)(r + 8) * N + c) = hi;
        }
    }
}

// ---------------------------------------------------------------------------
// Fused window attention v2: K-in-registers score + fused softmax + paired P@V.
// One block per (head h = blockIdx.x, window b = blockIdx.y), 8 warps.
// Each lane owns k[lane] and k[32+lane] in registers (j1 lanes < 17).
// Score row i: 8 broadcast q loads + register-K FMAs -> warp holds the full
// 49-score row -> shuffle softmax inline -> store NORMALIZED p to s.
// P@V: 2 rows per pass share each vt load.
// rel-pos idx = (ih-jh+6)*13 + (iw-jw+6); mask window = b % 64.
// ---------------------------------------------------------------------------
#define QP 36
#define SP 52
#define VP 52

__global__ __launch_bounds__(256) void win_attn(
    const float* __restrict__ qkv, const float* __restrict__ mask,
    const float* __restrict__ bt, float* __restrict__ out)
{
    __shared__ float q[NTOK][QP];
    __shared__ float k[NTOK][QP];
    __shared__ float vt[HD][VP];     // transposed: vt[d][n]
    __shared__ float s[NTOK][SP];    // normalized softmax weights
    __shared__ float btc[169];

    const int h   = blockIdx.x;
    const int b   = blockIdx.y;
    const int tid = threadIdx.x;
    const float scale = 0.17677669529663687f;   // 1/sqrt(32)

    const size_t base = (size_t)b * NTOK * QKVN + (size_t)h * HD;
    for (int idx = tid; idx < NTOK * HD; idx += 256) {
        int n = idx >> 5, d = idx & 31;
        size_t o = base + (size_t)n * QKVN + d;
        q[n][d]  = qkv[o] * scale;
        k[n][d]  = qkv[o + CDIM];
        vt[d][n] = qkv[o + 2 * CDIM];
    }
    for (int t = tid; t < 169; t += 256) btc[t] = bt[t * NH + h];
    __syncthreads();

    const int wid  = tid >> 5;
    const int lane = tid & 31;
    const float* mrow = mask + (size_t)(b & (NWIN - 1)) * NTOK * NTOK;

    // Per-lane j assignments: j0 = lane (always valid), j1 = 32+lane (lane<17)
    const bool has1 = lane < 17;
    const int  j0   = lane;
    const int  j1   = has1 ? 32 + lane : 0;   // safe index when inactive
    const int  j0h  = j0 / 7, j0w = j0 - 7 * j0h;
    const int  j1h  = j1 / 7, j1w = j1 - 7 * j1h;

    // K rows in registers (conflict-free: float4-pitch 9 is odd)
    float4 kr0[8], kr1[8];
    #pragma unroll
    for (int d4 = 0; d4 < 8; d4++) {
        kr0[d4] = *(const float4*)(&k[j0][d4 * 4]);
        kr1[d4] = *(const float4*)(&k[j1][d4 * 4]);
    }

    // ---- Scores + bias + mask + fused softmax (one pass per row) ----
    for (int i = wid; i < NTOK; i += 8) {
        const int ih = i / 7, iw = i - 7 * ih;
        float a0 = 0.0f, a1 = 0.0f;
        #pragma unroll
        for (int d4 = 0; d4 < 8; d4++) {
            float4 qv = *(const float4*)(&q[i][d4 * 4]);   // broadcast
            a0 = fmaf(qv.x, kr0[d4].x, a0); a0 = fmaf(qv.y, kr0[d4].y, a0);
            a0 = fmaf(qv.z, kr0[d4].z, a0); a0 = fmaf(qv.w, kr0[d4].w, a0);
            a1 = fmaf(qv.x, kr1[d4].x, a1); a1 = fmaf(qv.y, kr1[d4].y, a1);
            a1 = fmaf(qv.z, kr1[d4].z, a1); a1 = fmaf(qv.w, kr1[d4].w, a1);
        }
        a0 += btc[(ih - j0h + 6) * 13 + (iw - j0w + 6)] + mrow[i * NTOK + j0];
        if (has1) a1 += btc[(ih - j1h + 6) * 13 + (iw - j1w + 6)] + mrow[i * NTOK + j1];
        else      a1 = -1e30f;

        float m = fmaxf(a0, a1);
        #pragma unroll
        for (int o = 16; o > 0; o >>= 1) m = fmaxf(m, __shfl_xor_sync(0xffffffffu, m, o));
        float p0 = __expf(a0 - m);
        float p1 = has1 ? __expf(a1 - m) : 0.0f;
        float sum = p0 + p1;
        #pragma unroll
        for (int o = 16; o > 0; o >>= 1) sum += __shfl_xor_sync(0xffffffffu, sum, o);
        const float inv = 1.0f / sum;
        s[i][j0] = p0 * inv;
        if (has1) s[i][j1] = p1 * inv;
    }
    __syncthreads();

    // ---- P@V: 2 rows per pass share vt loads; lane = output channel d ----
    const float v48 = vt[lane][48];
    for (int t = wid; t < NTOK; t += 16) {
        const int i0 = t;
        const int i1 = t + 8;
        const bool h1 = i1 < NTOK;
        float a0 = 0.0f, a1 = 0.0f;
        #pragma unroll
        for (int j4 = 0; j4 < 12; j4++) {
            float4 vv = *(const float4*)(&vt[lane][j4 * 4]);   // conflict-free
            float4 s0 = *(const float4*)(&s[i0][j4 * 4]);      // broadcast
            a0 = fmaf(s0.x, vv.x, a0); a0 = fmaf(s0.y, vv.y, a0);
            a0 = fmaf(s0.z, vv.z, a0); a0 = fmaf(s0.w, vv.w, a0);
            if (h1) {
                float4 s1 = *(const float4*)(&s[i1][j4 * 4]);
                a1 = fmaf(s1.x, vv.x, a1); a1 = fmaf(s1.y, vv.y, a1);
                a1 = fmaf(s1.z, vv.z, a1); a1 = fmaf(s1.w, vv.w, a1);
            }
        }
        a0 = fmaf(s[i0][48], v48, a0);
        out[((size_t)b * NTOK + i0) * CDIM + (size_t)h * HD + lane] = a0;
        if (h1) {
            a1 = fmaf(s[i1][48], v48, a1);
            out[((size_t)b * NTOK + i1) * CDIM + (size_t)h * HD + lane] = a1;
        }
    }
}

// ---------------------------------------------------------------------------
// Launch: QKV GEMM -> fused attention -> proj GEMM
// ---------------------------------------------------------------------------
extern "C" void kernel_launch(void* const* d_in, const int* in_sizes, int n_in,
                              void* d_out, int out_size)
{
    const float* x      = (const float*)d_in[0];
    const float* mask   = (const float*)d_in[1];
    const float* qkv_w  = (const float*)d_in[2];
    const float* qkv_b  = (const float*)d_in[3];
    const float* proj_w = (const float*)d_in[4];
    const float* proj_b = (const float*)d_in[5];
    const float* btbl   = (const float*)d_in[6];
    float* out          = (float*)d_out;

    float *qkvp = nullptr, *attp = nullptr;
    cudaGetSymbolAddress((void**)&qkvp, g_qkv);
    cudaGetSymbolAddress((void**)&attp, g_att);

    // QKV: [200704 x 384] @ [384 x 1152] + bias
    gemm_bf16x3<<<dim3(QKVN / 128, MROWS / 128), 256>>>(
        x, qkv_w, qkv_b, qkvp, MROWS, QKVN, CDIM);

    // Fused window attention (one block per head x window)
    win_attn<<<dim3(NH, BSZ), 256>>>(qkvp, mask, btbl, attp);

    // Proj: [200704 x 384] @ [384 x 384] + bias
    gemm_bf16x3<<<dim3(CDIM / 128, MROWS / 128), 256>>>(
        attp, proj_w, proj_b, out, MROWS, CDIM, CDIM);
}